// round 1
// baseline (speedup 1.0000x reference)
#include <cuda_runtime.h>
#include <mma.h>
#include <cstdint>

using namespace nvcuda;

// Fixed problem shape (DistSparseMoe): T = 32768 tokens, H = 1024, E = 8.
#define T_MAX 32768
#define H_DIM 1024
#define E_DIM 8

// ---------------- scratch (no allocations allowed) ----------------
__device__ int   g_best [T_MAX];
__device__ float g_bestp[T_MAX];
__device__ int   g_order[T_MAX];
#define NB_MAX (T_MAX / 256)
__device__ int g_hist[NB_MAX * E_DIM];
__device__ int g_boff[NB_MAX * E_DIM];

// ---------------- cp.async helpers ----------------
__device__ __forceinline__ void cp_async16(void* smem_dst, const void* gmem_src) {
    unsigned s = (unsigned)__cvta_generic_to_shared(smem_dst);
    asm volatile("cp.async.cg.shared.global [%0], [%1], 16;\n" :: "r"(s), "l"(gmem_src));
}
__device__ __forceinline__ void cp_async_commit() {
    asm volatile("cp.async.commit_group;\n");
}
template <int N>
__device__ __forceinline__ void cp_async_wait() {
    asm volatile("cp.async.wait_group %0;\n" :: "n"(N));
}

// =====================================================================
// Kernel 1: router — logits, softmax prob of best expert, argmax.
// One token per warp iteration; warp-tree reduction keeps fp32 error low
// (~sqrt(32)*eps) to minimize argmax flips vs the reference.
// =====================================================================
__global__ __launch_bounds__(256) void router_kernel(
    const float* __restrict__ x, const float* __restrict__ Wr,
    const float* __restrict__ br, int T)
{
    __shared__ float sW[E_DIM][H_DIM];   // transposed router weights, 32 KB
    for (int i = threadIdx.x; i < H_DIM * E_DIM; i += 256) {
        int h = i >> 3, e = i & 7;       // W_router is [H, E] row-major
        sW[e][h] = Wr[i];
    }
    __syncthreads();

    int warp = threadIdx.x >> 5;
    int lane = threadIdx.x & 31;
    int tokBase = blockIdx.x * 32 + warp * 4;

    for (int tt = 0; tt < 4; ++tt) {
        int t = tokBase + tt;
        if (t >= T) break;
        const float* xr = x + (size_t)t * H_DIM;

        float acc[E_DIM];
        #pragma unroll
        for (int e = 0; e < E_DIM; ++e) acc[e] = 0.f;

        #pragma unroll 4
        for (int i = 0; i < H_DIM / 32; ++i) {
            float xv = xr[i * 32 + lane];
            #pragma unroll
            for (int e = 0; e < E_DIM; ++e)
                acc[e] += xv * sW[e][i * 32 + lane];
        }
        #pragma unroll
        for (int e = 0; e < E_DIM; ++e) {
            #pragma unroll
            for (int off = 16; off; off >>= 1)
                acc[e] += __shfl_down_sync(0xffffffffu, acc[e], off);
        }
        if (lane == 0) {
            float l[E_DIM];
            #pragma unroll
            for (int e = 0; e < E_DIM; ++e) l[e] = acc[e] + br[e];
            int bi = 0; float bm = l[0];
            #pragma unroll
            for (int e = 1; e < E_DIM; ++e)
                if (l[e] > bm) { bm = l[e]; bi = e; }   // first-max tie break
            float s = 0.f;
            #pragma unroll
            for (int e = 0; e < E_DIM; ++e) s += expf(l[e] - bm);
            g_best [t] = bi;
            g_bestp[t] = 1.0f / s;   // softmax prob of the best expert
        }
    }
}

// =====================================================================
// Kernel 2: per-block expert histograms (256 tokens / block)
// =====================================================================
__global__ void hist_kernel(int T)
{
    __shared__ int sh[E_DIM];
    if (threadIdx.x < E_DIM) sh[threadIdx.x] = 0;
    __syncthreads();
    int t = blockIdx.x * 256 + threadIdx.x;
    if (t < T) atomicAdd(&sh[g_best[t]], 1);
    __syncthreads();
    if (threadIdx.x < E_DIM)
        g_hist[blockIdx.x * E_DIM + threadIdx.x] = sh[threadIdx.x];
}

// =====================================================================
// Kernel 3: exclusive offsets (single block; 8 active threads, cheap)
// =====================================================================
__global__ void offsets_kernel(int NB)
{
    __shared__ int tot[E_DIM];
    int e = threadIdx.x;
    if (e < E_DIM) {
        int s = 0;
        for (int b = 0; b < NB; ++b) {
            int v = g_hist[b * E_DIM + e];
            g_boff[b * E_DIM + e] = s;
            s += v;
        }
        tot[e] = s;
    }
    __syncthreads();
    if (e < E_DIM) {
        int base = 0;
        for (int ee = 0; ee < e; ++ee) base += tot[ee];
        for (int b = 0; b < NB; ++b) g_boff[b * E_DIM + e] += base;
    }
}

// =====================================================================
// Kernel 4: stable scatter — order[pos] = token (counting-sort = stable
// argsort, matching jnp.argsort's stability exactly)
// =====================================================================
__global__ void scatter_kernel(int T)
{
    __shared__ int sb[256];
    int i = threadIdx.x;
    int t = blockIdx.x * 256 + i;
    sb[i] = (t < T) ? g_best[t] : -1;
    __syncthreads();
    if (t < T) {
        int e = sb[i];
        int rank = 0;
        for (int j = 0; j < i; ++j) rank += (sb[j] == e);  // smem broadcast loop
        int pos = g_boff[blockIdx.x * E_DIM + e] + rank;
        g_order[pos] = t;
    }
}

// =====================================================================
// Kernel 5: gathered GEMM + bias + best_p scaling, WMMA tf32.
// out[t, :] = (x[order[t], :] @ W_expert + b_expert) * bestp[t]
// Block tile 128x128, BK=16, 8 warps (2M x 4N), cp.async double buffer.
// =====================================================================
#define BM 128
#define BN 128
#define BK 16
#define LDA 20      // padded, multiple of 4 (keeps 16B row alignment)
#define LDB 132     // padded, multiple of 4
#define NKT (H_DIM / BK)   // 64

__global__ __launch_bounds__(256) void gemm_kernel(
    const float* __restrict__ x, const float* __restrict__ We,
    const float* __restrict__ be, float* __restrict__ out, int T)
{
    __shared__ float As[2][BM * LDA];   // 20480 B
    __shared__ float Bs[2][BK * LDB];   // 16896 B
    __shared__ float sC[8][256];        //  8192 B, per-warp epilogue staging
    __shared__ float sBias[BN];
    __shared__ float sBp[BM];

    const int tid = threadIdx.x;
    const int rowBase = blockIdx.y * BM;
    const int colBase = blockIdx.x * BN;

    if (tid < BM)       sBp[tid]        = g_bestp[rowBase + tid];
    else                sBias[tid - BM] = be[colBase + tid - BM];

    // A-load mapping: 128 rows x 16 cols per tile; 2 threads/row, 2x16B each
    const int arow = tid >> 1;
    const int aseg = (tid & 1) * 8;
    const int gRow = g_order[rowBase + arow];
    const float* aSrc = x + (size_t)gRow * H_DIM + aseg;

    // B-load mapping: 16 rows x 128 cols; each thread 32 contiguous bytes
    const int bIdx  = tid * 2;
    const int bRow  = bIdx >> 5;          // 0..15
    const int bCol  = (bIdx & 31) * 4;    // 0..124, step 8

    auto load_tiles = [&](int buf, int kt) {
        const int k0 = kt * BK;
        cp_async16(&As[buf][arow * LDA + aseg + 0], aSrc + k0 + 0);
        cp_async16(&As[buf][arow * LDA + aseg + 4], aSrc + k0 + 4);
        const float* bSrc = We + (size_t)(k0 + bRow) * H_DIM + colBase + bCol;
        cp_async16(&Bs[buf][bRow * LDB + bCol + 0], bSrc + 0);
        cp_async16(&Bs[buf][bRow * LDB + bCol + 4], bSrc + 4);
    };

    const int warpId = tid >> 5;
    const int wm = warpId >> 2;      // 0..1  -> 64-row slab
    const int wn = warpId & 3;       // 0..3  -> 32-col slab

    wmma::fragment<wmma::accumulator, 16, 16, 8, float> acc[4][2];
    #pragma unroll
    for (int mi = 0; mi < 4; ++mi)
        #pragma unroll
        for (int ni = 0; ni < 2; ++ni)
            wmma::fill_fragment(acc[mi][ni], 0.0f);

    // prologue
    load_tiles(0, 0);
    cp_async_commit();

    for (int kt = 0; kt < NKT; ++kt) {
        if (kt + 1 < NKT) {
            load_tiles((kt + 1) & 1, kt + 1);
            cp_async_commit();
            cp_async_wait<1>();
        } else {
            cp_async_wait<0>();
        }
        __syncthreads();

        const int buf = kt & 1;
        #pragma unroll
        for (int ks = 0; ks < 2; ++ks) {
            wmma::fragment<wmma::matrix_a, 16, 16, 8, wmma::precision::tf32,
                           wmma::row_major> af[4];
            wmma::fragment<wmma::matrix_b, 16, 16, 8, wmma::precision::tf32,
                           wmma::row_major> bf[2];
            #pragma unroll
            for (int mi = 0; mi < 4; ++mi) {
                wmma::load_matrix_sync(
                    af[mi], &As[buf][(wm * 64 + mi * 16) * LDA + ks * 8], LDA);
                #pragma unroll
                for (int i = 0; i < af[mi].num_elements; ++i)
                    af[mi].x[i] = wmma::__float_to_tf32(af[mi].x[i]);  // RN, not RZ!
            }
            #pragma unroll
            for (int ni = 0; ni < 2; ++ni) {
                wmma::load_matrix_sync(
                    bf[ni], &Bs[buf][(ks * 8) * LDB + wn * 32 + ni * 16], LDB);
                #pragma unroll
                for (int i = 0; i < bf[ni].num_elements; ++i)
                    bf[ni].x[i] = wmma::__float_to_tf32(bf[ni].x[i]);
            }
            #pragma unroll
            for (int mi = 0; mi < 4; ++mi)
                #pragma unroll
                for (int ni = 0; ni < 2; ++ni)
                    wmma::mma_sync(acc[mi][ni], af[mi], bf[ni], acc[mi][ni]);
        }
        __syncthreads();
    }

    // epilogue: (acc + bias) * bestp, via per-warp 16x16 staging
    const int lane = tid & 31;
    float* stg = &sC[warpId][0];
    #pragma unroll
    for (int mi = 0; mi < 4; ++mi) {
        #pragma unroll
        for (int ni = 0; ni < 2; ++ni) {
            wmma::store_matrix_sync(stg, acc[mi][ni], 16, wmma::mem_row_major);
            __syncwarp();
            const int r = lane >> 1;
            const int c = (lane & 1) * 8;
            const int rowL = wm * 64 + mi * 16 + r;
            const int colL = wn * 32 + ni * 16 + c;
            const int t = rowBase + rowL;
            const float p = sBp[rowL];
            float4 v0 = *(const float4*)&stg[r * 16 + c];
            float4 v1 = *(const float4*)&stg[r * 16 + c + 4];
            float4 o0, o1;
            o0.x = (v0.x + sBias[colL + 0]) * p;
            o0.y = (v0.y + sBias[colL + 1]) * p;
            o0.z = (v0.z + sBias[colL + 2]) * p;
            o0.w = (v0.w + sBias[colL + 3]) * p;
            o1.x = (v1.x + sBias[colL + 4]) * p;
            o1.y = (v1.y + sBias[colL + 5]) * p;
            o1.z = (v1.z + sBias[colL + 6]) * p;
            o1.w = (v1.w + sBias[colL + 7]) * p;
            float* dst = out + (size_t)t * H_DIM + colBase + colL;
            *(float4*)(dst + 0) = o0;
            *(float4*)(dst + 4) = o1;
            __syncwarp();
        }
    }
}

// =====================================================================
// launch
// =====================================================================
extern "C" void kernel_launch(void* const* d_in, const int* in_sizes, int n_in,
                              void* d_out, int out_size)
{
    const float* x  = (const float*)d_in[0];
    const float* Wr = (const float*)d_in[1];
    const float* br = (const float*)d_in[2];
    const float* We = (const float*)d_in[3];
    const float* be = (const float*)d_in[4];
    float* out = (float*)d_out;

    const int T  = in_sizes[0] / H_DIM;   // 32768
    const int NB = T / 256;               // 128

    router_kernel<<<T / 32, 256>>>(x, Wr, br, T);
    hist_kernel<<<NB, 256>>>(T);
    offsets_kernel<<<1, 32>>>(NB);
    scatter_kernel<<<NB, 256>>>(T);

    dim3 grid(H_DIM / BN, T / BM);        // nTile fastest -> L2 reuse of gathered A rows
    gemm_kernel<<<grid, 256>>>(x, We, be, out, T);
}

// round 4
// speedup vs baseline: 2.9757x; 2.9757x over previous
#include <cuda_runtime.h>
#include <mma.h>
#include <cstdint>

using namespace nvcuda;

#define T_MAX 32768
#define H_DIM 1024
#define E_DIM 8

// tcgen05 is only legal in arch-accelerated (sm_10xa) compilation passes.
#if defined(__CUDA_ARCH_FEAT_SM103_ALL) || defined(__CUDA_ARCH_FEAT_SM100_ALL) || defined(__CUDA_ARCH_FEAT_SM101_ALL)
#define HAS_TCGEN05 1
#else
#define HAS_TCGEN05 0
#endif

// ---------------- scratch (no runtime allocations allowed) ----------------
__device__ int   g_best [T_MAX];
__device__ float g_bestp[T_MAX];
__device__ int   g_order[T_MAX];
#define NB_MAX (T_MAX / 256)
__device__ int g_hist[NB_MAX * E_DIM];
__device__ int g_boff[NB_MAX * E_DIM];
__device__ float g_A [T_MAX * H_DIM];   // gathered + RN-rounded-to-tf32 activations
__device__ float g_Wt[H_DIM * H_DIM];   // W_expert transposed ([N,K]) + RN tf32

// ---------------- generic helpers (legal on all targets) ----------------
__device__ __forceinline__ uint32_t smem_u32(const void* p) {
    uint32_t a;
    asm("{ .reg .u64 t; cvta.to.shared.u64 t, %1; cvt.u32.u64 %0, t; }" : "=r"(a) : "l"(p));
    return a;
}
__device__ __forceinline__ float round_tf32(float v) {
    uint32_t o;
    asm("cvt.rna.tf32.f32 %0, %1;" : "=r"(o) : "f"(v));
    return __uint_as_float(o);
}
__device__ __forceinline__ void cp16(uint32_t saddr, const void* g) {
    asm volatile("cp.async.cg.shared.global [%0], [%1], 16;\n" :: "r"(saddr), "l"(g));
}
__device__ __forceinline__ void cp_commit() { asm volatile("cp.async.commit_group;\n"); }
template <int N> __device__ __forceinline__ void cp_wait() {
    asm volatile("cp.async.wait_group %0;\n" :: "n"(N));
}
#define SWZ(o) ((o) ^ (((o) >> 3) & 0x70))

__device__ __forceinline__ uint32_t elect_one_pred() {
    uint32_t pred;
    asm volatile(
        "{\n\t.reg .pred p;\n\t"
        "elect.sync _|p, 0xFFFFFFFF;\n\t"
        "selp.b32 %0, 1, 0, p;\n\t}"
        : "=r"(pred));
    return pred;
}

// =====================================================================
// Kernel 1: router
// =====================================================================
__global__ __launch_bounds__(256) void router_kernel(
    const float* __restrict__ x, const float* __restrict__ Wr,
    const float* __restrict__ br, int T)
{
    __shared__ float sW[E_DIM][H_DIM];
    for (int i = threadIdx.x; i < H_DIM * E_DIM; i += 256) {
        int h = i >> 3, e = i & 7;
        sW[e][h] = Wr[i];
    }
    __syncthreads();

    int warp = threadIdx.x >> 5;
    int lane = threadIdx.x & 31;
    int tokBase = blockIdx.x * 32 + warp * 4;

    for (int tt = 0; tt < 4; ++tt) {
        int t = tokBase + tt;
        if (t >= T) break;
        const float* xr = x + (size_t)t * H_DIM;

        float acc[E_DIM];
        #pragma unroll
        for (int e = 0; e < E_DIM; ++e) acc[e] = 0.f;
        #pragma unroll 4
        for (int i = 0; i < H_DIM / 32; ++i) {
            float xv = xr[i * 32 + lane];
            #pragma unroll
            for (int e = 0; e < E_DIM; ++e) acc[e] += xv * sW[e][i * 32 + lane];
        }
        #pragma unroll
        for (int e = 0; e < E_DIM; ++e) {
            #pragma unroll
            for (int off = 16; off; off >>= 1)
                acc[e] += __shfl_down_sync(0xffffffffu, acc[e], off);
        }
        if (lane == 0) {
            float l[E_DIM];
            #pragma unroll
            for (int e = 0; e < E_DIM; ++e) l[e] = acc[e] + br[e];
            int bi = 0; float bm = l[0];
            #pragma unroll
            for (int e = 1; e < E_DIM; ++e)
                if (l[e] > bm) { bm = l[e]; bi = e; }
            float s = 0.f;
            #pragma unroll
            for (int e = 0; e < E_DIM; ++e) s += expf(l[e] - bm);
            g_best [t] = bi;
            g_bestp[t] = 1.0f / s;
        }
    }
}

// =====================================================================
// Kernels 2-4: stable counting sort (matches jnp.argsort stability)
// =====================================================================
__global__ void hist_kernel(int T)
{
    __shared__ int sh[E_DIM];
    if (threadIdx.x < E_DIM) sh[threadIdx.x] = 0;
    __syncthreads();
    int t = blockIdx.x * 256 + threadIdx.x;
    if (t < T) atomicAdd(&sh[g_best[t]], 1);
    __syncthreads();
    if (threadIdx.x < E_DIM)
        g_hist[blockIdx.x * E_DIM + threadIdx.x] = sh[threadIdx.x];
}

__global__ void offsets_kernel(int NB)
{
    __shared__ int tot[E_DIM];
    int e = threadIdx.x;
    if (e < E_DIM) {
        int s = 0;
        for (int b = 0; b < NB; ++b) {
            int v = g_hist[b * E_DIM + e];
            g_boff[b * E_DIM + e] = s;
            s += v;
        }
        tot[e] = s;
    }
    __syncthreads();
    if (e < E_DIM) {
        int base = 0;
        for (int ee = 0; ee < e; ++ee) base += tot[ee];
        for (int b = 0; b < NB; ++b) g_boff[b * E_DIM + e] += base;
    }
}

__global__ void scatter_kernel(int T)
{
    __shared__ int sb[256];
    int i = threadIdx.x;
    int t = blockIdx.x * 256 + i;
    sb[i] = (t < T) ? g_best[t] : -1;
    __syncthreads();
    if (t < T) {
        int e = sb[i];
        int rank = 0;
        for (int j = 0; j < i; ++j) rank += (sb[j] == e);
        int pos = g_boff[blockIdx.x * E_DIM + e] + rank;
        g_order[pos] = t;
    }
}

// =====================================================================
// Kernel 5: gather permuted rows of x, RN-round to tf32  (A_perm)
// =====================================================================
__global__ __launch_bounds__(256) void gather_round_kernel(const float* __restrict__ x)
{
    int t = blockIdx.x;
    int src = g_order[t];
    const float4* s = (const float4*)(x + (size_t)src * H_DIM);
    float4* d = (float4*)(g_A + (size_t)t * H_DIM);
    float4 v = s[threadIdx.x];
    v.x = round_tf32(v.x); v.y = round_tf32(v.y);
    v.z = round_tf32(v.z); v.w = round_tf32(v.w);
    d[threadIdx.x] = v;
}

// =====================================================================
// Kernel 6: transpose W_expert -> [N,K] with RN tf32 rounding
// =====================================================================
__global__ void transpose_round_kernel(const float* __restrict__ We)
{
    __shared__ float tile[32][33];
    int n = blockIdx.x * 32 + threadIdx.x;
    int k = blockIdx.y * 32 + threadIdx.y;
    tile[threadIdx.y][threadIdx.x] = round_tf32(We[(size_t)k * H_DIM + n]);
    __syncthreads();
    int on = blockIdx.x * 32 + threadIdx.y;
    int ok = blockIdx.y * 32 + threadIdx.x;
    g_Wt[(size_t)on * H_DIM + ok] = tile[threadIdx.x][threadIdx.y];
}

// =====================================================================
// tcgen05-only machinery
// =====================================================================
#if HAS_TCGEN05

#define MBARRIER_INIT(addr, cnt) \
    asm volatile("mbarrier.init.shared.b64 [%0], %1;" :: "r"((uint32_t)(addr)), "r"((uint32_t)(cnt)) : "memory")
#define MBARRIER_INVAL(addr) \
    asm volatile("mbarrier.inval.shared.b64 [%0];" :: "r"((uint32_t)(addr)) : "memory")
#define MBARRIER_WAIT_PARITY(mbar, parity) do {                                   \
    asm volatile(                                                                 \
        "{\n\t.reg .pred P1;\n\t"                                                 \
        "WAIT_LOOP_%=:\n\t"                                                       \
        "mbarrier.try_wait.parity.acquire.cta.shared::cta.b64 P1, [%0], %1, 0x989680;\n\t" \
        "@P1 bra.uni WAIT_DONE_%=;\n\t"                                           \
        "bra.uni WAIT_LOOP_%=;\n\t"                                               \
        "WAIT_DONE_%=:\n\t}"                                                      \
        :: "r"((uint32_t)(mbar)), "r"((uint32_t)(parity)) : "memory");            \
} while (0)

#define TCGEN05_ALLOC(sres, n) \
    asm volatile("tcgen05.alloc.cta_group::1.sync.aligned.shared::cta.b32 [%0], %1;" \
                 :: "r"((uint32_t)(sres)), "r"((uint32_t)(n)) : "memory")
#define TCGEN05_DEALLOC(tm, n) \
    asm volatile("tcgen05.dealloc.cta_group::1.sync.aligned.b32 %0, %1;" :: "r"(tm), "r"((uint32_t)(n)))
#define TCGEN05_COMMIT(mbar) \
    asm volatile("tcgen05.commit.cta_group::1.mbarrier::arrive::one.shared::cluster.b64 [%0];" \
                 :: "r"((uint32_t)(mbar)) : "memory")
#define TCGEN05_FENCE_AFTER()  asm volatile("tcgen05.fence::after_thread_sync;" ::: "memory")
#define TCGEN05_FENCE_BEFORE() asm volatile("tcgen05.fence::before_thread_sync;" ::: "memory")
#define TCGEN05_WAIT_LD()      asm volatile("tcgen05.wait::ld.sync.aligned;" ::: "memory")
#define FENCE_PROXY_ASYNC()    asm volatile("fence.proxy.async.shared::cta;" ::: "memory")

#define TCGEN05_LD_32X32B_X32(r, tmem_addr)                                     \
    asm volatile(                                                               \
        "tcgen05.ld.sync.aligned.32x32b.x32.b32 "                               \
        "{%0, %1, %2, %3, %4, %5, %6, %7, "                                     \
        " %8, %9, %10, %11, %12, %13, %14, %15, "                               \
        " %16, %17, %18, %19, %20, %21, %22, %23, "                             \
        " %24, %25, %26, %27, %28, %29, %30, %31}, [%32];"                      \
        : "=r"((r)[0]),  "=r"((r)[1]),  "=r"((r)[2]),  "=r"((r)[3]),            \
          "=r"((r)[4]),  "=r"((r)[5]),  "=r"((r)[6]),  "=r"((r)[7]),            \
          "=r"((r)[8]),  "=r"((r)[9]),  "=r"((r)[10]), "=r"((r)[11]),           \
          "=r"((r)[12]), "=r"((r)[13]), "=r"((r)[14]), "=r"((r)[15]),           \
          "=r"((r)[16]), "=r"((r)[17]), "=r"((r)[18]), "=r"((r)[19]),           \
          "=r"((r)[20]), "=r"((r)[21]), "=r"((r)[22]), "=r"((r)[23]),           \
          "=r"((r)[24]), "=r"((r)[25]), "=r"((r)[26]), "=r"((r)[27]),           \
          "=r"((r)[28]), "=r"((r)[29]), "=r"((r)[30]), "=r"((r)[31])            \
        : "r"(tmem_addr))

static constexpr uint64_t SMEM_DESC_BASE_SW128 =
    (uint64_t(2)  << 61) | (uint64_t(1) << 46) | (uint64_t(64) << 32) | (uint64_t(1) << 16);
#define MAKE_SMEM_DESC(base) (SMEM_DESC_BASE_SW128 | ((uint64_t)((base) >> 4) & 0x3FFF))

// idesc kind::tf32 SS cg1: d=F32(1<<4), a=TF32(2<<7), b=TF32(2<<10),
// (N=256/8)<<17, (M=128/16)<<24.
// (Formula validated: reproduces test_mma.cu's known-good 0x8080490 for bf16/N=32/M=128.)
#define GEMM_IDESC 0x8400910u

__device__ __forceinline__ void mma_tf32_ss(uint32_t d, uint64_t a, uint64_t b, uint32_t en) {
    asm volatile(
        "{\n\t.reg .pred p;\n\t"
        "setp.ne.u32 p, %4, 0;\n\t"
        "tcgen05.mma.cta_group::1.kind::tf32 [%0], %1, %2, %3, {%5, %5, %5, %5}, p;\n\t}"
        :: "r"(d), "l"(a), "l"(b), "r"(GEMM_IDESC), "r"(en), "r"(0u) : "memory");
}
#endif  // HAS_TCGEN05

// =====================================================================
// Kernel 7a: tcgen05 tf32 GEMM 128x256 (body only in 'a' builds)
// =====================================================================
#define GBM 128
#define GBN 256
#define GBK 32
#define A_STAGE (GBM * GBK * 4)
#define B_STAGE (GBN * GBK * 4)
#define GEMM_SMEM 102400

__global__ __launch_bounds__(256)
#if HAS_TCGEN05
__cluster_dims__(1, 1, 1)
#endif
void gemm_tc_kernel(const float* __restrict__ be, float* __restrict__ out)
{
#if HAS_TCGEN05
    extern __shared__ char smem[];
    uint32_t sb = smem_u32(smem);
    const int tid  = threadIdx.x;
    const int wid  = tid >> 5;
    const int lane = tid & 31;
    const int rowBase = blockIdx.y * GBM;
    const int colBase = blockIdx.x * GBN;

    float* sBias = (float*)(smem + 64);
    float* sBp   = (float*)(smem + 1088);
    const uint32_t abase = (sb + 2048 + 1023) & ~1023u;
    const uint32_t bbase = abase + 2 * A_STAGE;

    // lifecycle exactly as in the working examples: warp 0 allocs, no relinquish
    if (wid == 0) {
        TCGEN05_ALLOC(sb + 0, 256);
        if (elect_one_pred()) { MBARRIER_INIT(sb + 8, 1); MBARRIER_INIT(sb + 16, 1); }
    }
    sBias[tid] = be[colBase + tid];
    if (tid < GBM) sBp[tid] = g_bestp[rowBase + tid];
    __syncthreads();
    uint32_t tmem;
    asm volatile("ld.shared.b32 %0, [%1];" : "=r"(tmem) : "r"(sb + 0));

    const float* Abase = g_A  + (size_t)rowBase * H_DIM;
    const float* Bbase = g_Wt + (size_t)colBase * H_DIM;

    auto load_stage = [&](int buf, int kt) {
        const int k0 = kt * GBK;
        #pragma unroll
        for (int j = 0; j < 4; ++j) {
            int idx = tid + j * 256;
            int r = idx >> 3, s = idx & 7;
            cp16(abase + buf * A_STAGE + SWZ(r * 128 + s * 16),
                 Abase + (size_t)r * H_DIM + k0 + s * 4);
        }
        #pragma unroll
        for (int j = 0; j < 8; ++j) {
            int idx = tid + j * 256;
            int r = idx >> 3, s = idx & 7;
            cp16(bbase + buf * B_STAGE + SWZ(r * 128 + s * 16),
                 Bbase + (size_t)r * H_DIM + k0 + s * 4);
        }
    };

    int ph0 = 0, ph1 = 0;
    load_stage(0, 0);
    cp_commit();

    const uint64_t adb = MAKE_SMEM_DESC(abase);
    const uint64_t bdb = MAKE_SMEM_DESC(bbase);

    const int NSTAGE = H_DIM / GBK;   // 32
    for (int kt = 0; kt < NSTAGE; ++kt) {
        const int cur = kt & 1;
        if (kt + 1 < NSTAGE) {
            const int nb = cur ^ 1;
            if (kt >= 1) {  // buffer nb was read by MMA of stage kt-1; wait for it
                if (nb == 0) { MBARRIER_WAIT_PARITY(sb + 8,  ph0); ph0 ^= 1; }
                else         { MBARRIER_WAIT_PARITY(sb + 16, ph1); ph1 ^= 1; }
            }
            load_stage(nb, kt + 1);
            cp_commit();
            cp_wait<1>();
        } else {
            cp_wait<0>();
        }
        FENCE_PROXY_ASYNC();   // make cp.async fills visible to the async proxy
        __syncthreads();

        if (wid == 0) {
            if (elect_one_pred()) {
                uint64_t ad = adb + (uint64_t)cur * (A_STAGE >> 4);
                uint64_t bd = bdb + (uint64_t)cur * (B_STAGE >> 4);
                #pragma unroll
                for (int ks = 0; ks < 4; ++ks)   // 4 x K=8 per 32-wide stage
                    mma_tf32_ss(tmem, ad + ks * 2, bd + ks * 2, (kt | ks) != 0);
                TCGEN05_COMMIT(sb + 8 + cur * 8);
            }
        }
    }

    MBARRIER_WAIT_PARITY(sb + 8,  ph0);
    MBARRIER_WAIT_PARITY(sb + 16, ph1);
    TCGEN05_FENCE_AFTER();

    if (wid < 4) {
        const float p = sBp[wid * 32 + lane];
        float* orow = out + (size_t)(rowBase + wid * 32 + lane) * H_DIM + colBase;
        #pragma unroll
        for (int ch = 0; ch < 8; ++ch) {
            uint32_t r[32];
            TCGEN05_LD_32X32B_X32(r, tmem + ch * 32);
            TCGEN05_WAIT_LD();
            #pragma unroll
            for (int i = 0; i < 32; i += 4) {
                float4 v;
                v.x = (__uint_as_float(r[i + 0]) + sBias[ch * 32 + i + 0]) * p;
                v.y = (__uint_as_float(r[i + 1]) + sBias[ch * 32 + i + 1]) * p;
                v.z = (__uint_as_float(r[i + 2]) + sBias[ch * 32 + i + 2]) * p;
                v.w = (__uint_as_float(r[i + 3]) + sBias[ch * 32 + i + 3]) * p;
                *(float4*)(orow + ch * 32 + i) = v;
            }
        }
        TCGEN05_FENCE_BEFORE();
    }
    __syncthreads();
    if (wid == 0) {
        if (elect_one_pred()) { MBARRIER_INVAL(sb + 8); MBARRIER_INVAL(sb + 16); }
        TCGEN05_DEALLOC(tmem, 256);
    }
#endif  // HAS_TCGEN05
}

// =====================================================================
// Kernel 7b: WMMA tf32 fallback 128x128 (compiled in ALL passes).
// A from g_A (pre-gathered, pre-rounded), B from g_Wt ([N,K], pre-rounded)
// =====================================================================
#define FBM 128
#define FBN 128
#define FBK 16
#define FLD 20
#define FNKT (H_DIM / FBK)
#define FB_SMEM (( (2*FBM*FLD) + (2*FBN*FLD) + 8*256 + FBM + FBN ) * 4)

__global__ __launch_bounds__(256) void gemm_wmma_kernel(
    const float* __restrict__ be, float* __restrict__ out)
{
    extern __shared__ float fsm[];
    float* As    = fsm;
    float* Bs    = As + 2 * FBM * FLD;
    float* sC    = Bs + 2 * FBN * FLD;
    float* sBias = sC + 8 * 256;
    float* sBp   = sBias + FBN;

    const int tid = threadIdx.x;
    const int rowBase = blockIdx.y * FBM;
    const int colBase = blockIdx.x * FBN;

    if (tid < FBM)       sBp[tid]         = g_bestp[rowBase + tid];
    else                 sBias[tid - FBM] = be[colBase + tid - FBM];

    const int arow = tid >> 1;
    const int aseg = (tid & 1) * 8;
    const float* aSrc = g_A  + (size_t)(rowBase + arow) * H_DIM + aseg;
    const float* bSrc = g_Wt + (size_t)(colBase + arow) * H_DIM + aseg;
    const uint32_t asm_base = smem_u32(As);
    const uint32_t bsm_base = smem_u32(Bs);

    auto load_tiles = [&](int buf, int kt) {
        const int k0 = kt * FBK;
        uint32_t ao = asm_base + (buf * FBM * FLD + arow * FLD + aseg) * 4;
        uint32_t bo = bsm_base + (buf * FBN * FLD + arow * FLD + aseg) * 4;
        cp16(ao,      aSrc + k0);
        cp16(ao + 16, aSrc + k0 + 4);
        cp16(bo,      bSrc + k0);
        cp16(bo + 16, bSrc + k0 + 4);
    };

    const int warpId = tid >> 5;
    const int wm = warpId >> 2;
    const int wn = warpId & 3;

    wmma::fragment<wmma::accumulator, 16, 16, 8, float> acc[4][2];
    #pragma unroll
    for (int mi = 0; mi < 4; ++mi)
        #pragma unroll
        for (int ni = 0; ni < 2; ++ni)
            wmma::fill_fragment(acc[mi][ni], 0.0f);

    load_tiles(0, 0);
    cp_commit();

    for (int kt = 0; kt < FNKT; ++kt) {
        if (kt + 1 < FNKT) {
            load_tiles((kt + 1) & 1, kt + 1);
            cp_commit();
            cp_wait<1>();
        } else {
            cp_wait<0>();
        }
        __syncthreads();

        const int buf = kt & 1;
        #pragma unroll
        for (int ks = 0; ks < 2; ++ks) {
            wmma::fragment<wmma::matrix_a, 16, 16, 8, wmma::precision::tf32,
                           wmma::row_major> af[4];
            wmma::fragment<wmma::matrix_b, 16, 16, 8, wmma::precision::tf32,
                           wmma::col_major> bf[2];
            #pragma unroll
            for (int mi = 0; mi < 4; ++mi)
                wmma::load_matrix_sync(
                    af[mi], &As[buf * FBM * FLD + (wm * 64 + mi * 16) * FLD + ks * 8], FLD);
            #pragma unroll
            for (int ni = 0; ni < 2; ++ni)
                wmma::load_matrix_sync(
                    bf[ni], &Bs[buf * FBN * FLD + (wn * 32 + ni * 16) * FLD + ks * 8], FLD);
            #pragma unroll
            for (int mi = 0; mi < 4; ++mi)
                #pragma unroll
                for (int ni = 0; ni < 2; ++ni)
                    wmma::mma_sync(acc[mi][ni], af[mi], bf[ni], acc[mi][ni]);
        }
        __syncthreads();
    }

    const int lane = tid & 31;
    float* stg = &sC[warpId * 256];
    #pragma unroll
    for (int mi = 0; mi < 4; ++mi) {
        #pragma unroll
        for (int ni = 0; ni < 2; ++ni) {
            wmma::store_matrix_sync(stg, acc[mi][ni], 16, wmma::mem_row_major);
            __syncwarp();
            const int r = lane >> 1;
            const int c = (lane & 1) * 8;
            const int rowL = wm * 64 + mi * 16 + r;
            const int colL = wn * 32 + ni * 16 + c;
            const float p = sBp[rowL];
            float4 v0 = *(const float4*)&stg[r * 16 + c];
            float4 v1 = *(const float4*)&stg[r * 16 + c + 4];
            float4 o0, o1;
            o0.x = (v0.x + sBias[colL + 0]) * p;
            o0.y = (v0.y + sBias[colL + 1]) * p;
            o0.z = (v0.z + sBias[colL + 2]) * p;
            o0.w = (v0.w + sBias[colL + 3]) * p;
            o1.x = (v1.x + sBias[colL + 4]) * p;
            o1.y = (v1.y + sBias[colL + 5]) * p;
            o1.z = (v1.z + sBias[colL + 6]) * p;
            o1.w = (v1.w + sBias[colL + 7]) * p;
            float* dst = out + (size_t)(rowBase + rowL) * H_DIM + colBase + colL;
            *(float4*)(dst + 0) = o0;
            *(float4*)(dst + 4) = o1;
            __syncwarp();
        }
    }
}

// =====================================================================
// launch — pick exactly ONE GEMM based on which binary variant loaded.
// An empty-body kernel has ~2-6 registers; the real tc kernel needs >>32.
// cudaFuncGetAttributes is a host query (capture-legal, deterministic).
// =====================================================================
extern "C" void kernel_launch(void* const* d_in, const int* in_sizes, int n_in,
                              void* d_out, int out_size)
{
    const float* x  = (const float*)d_in[0];
    const float* Wr = (const float*)d_in[1];
    const float* br = (const float*)d_in[2];
    const float* We = (const float*)d_in[3];
    const float* be = (const float*)d_in[4];
    float* out = (float*)d_out;

    const int T  = in_sizes[0] / H_DIM;   // 32768
    const int NB = T / 256;

    router_kernel<<<T / 32, 256>>>(x, Wr, br, T);
    transpose_round_kernel<<<dim3(H_DIM / 32, H_DIM / 32), dim3(32, 32)>>>(We);
    hist_kernel<<<NB, 256>>>(T);
    offsets_kernel<<<1, 32>>>(NB);
    scatter_kernel<<<NB, 256>>>(T);
    gather_round_kernel<<<T, 256>>>(x);

    cudaFuncAttributes attr;
    attr.numRegs = 0;
    cudaFuncGetAttributes(&attr, (const void*)gemm_tc_kernel);

    if (attr.numRegs > 32) {
        // tcgen05 path present in the loaded binary
        cudaFuncSetAttribute(gemm_tc_kernel,
                             cudaFuncAttributeMaxDynamicSharedMemorySize, GEMM_SMEM);
        dim3 gtc(H_DIM / GBN, T / GBM);   // (4, 256)
        gemm_tc_kernel<<<gtc, 256, GEMM_SMEM>>>(be, out);
    } else {
        cudaFuncSetAttribute(gemm_wmma_kernel,
                             cudaFuncAttributeMaxDynamicSharedMemorySize, FB_SMEM);
        dim3 gfb(H_DIM / FBN, T / FBM);   // (8, 256)
        gemm_wmma_kernel<<<gfb, 256, FB_SMEM>>>(be, out);
    }
}

// round 5
// speedup vs baseline: 3.2427x; 1.0897x over previous
#include <cuda_runtime.h>
#include <mma.h>
#include <cstdint>

using namespace nvcuda;

#define T_MAX 32768
#define H_DIM 1024
#define E_DIM 8

// tcgen05 is only legal in arch-accelerated (sm_10xa) compilation passes.
#if defined(__CUDA_ARCH_FEAT_SM103_ALL) || defined(__CUDA_ARCH_FEAT_SM100_ALL) || defined(__CUDA_ARCH_FEAT_SM101_ALL)
#define HAS_TCGEN05 1
#else
#define HAS_TCGEN05 0
#endif

// ---------------- scratch (no runtime allocations allowed) ----------------
__device__ int   g_best [T_MAX];
__device__ float g_bestp[T_MAX];
__device__ int   g_order[T_MAX];
#define NB_MAX (T_MAX / 256)
__device__ int g_hist[NB_MAX * E_DIM];
__device__ int g_boff[NB_MAX * E_DIM];
__device__ float g_A [T_MAX * H_DIM];   // gathered + RN-rounded-to-tf32 activations
__device__ float g_Wt[H_DIM * H_DIM];   // W_expert transposed ([N,K]) + RN tf32

// ---------------- generic helpers ----------------
__device__ __forceinline__ uint32_t smem_u32(const void* p) {
    uint32_t a;
    asm("{ .reg .u64 t; cvta.to.shared.u64 t, %1; cvt.u32.u64 %0, t; }" : "=r"(a) : "l"(p));
    return a;
}
__device__ __forceinline__ float round_tf32(float v) {
    uint32_t o;
    asm("cvt.rna.tf32.f32 %0, %1;" : "=r"(o) : "f"(v));
    return __uint_as_float(o);
}
__device__ __forceinline__ void cp16(uint32_t saddr, const void* g) {
    asm volatile("cp.async.cg.shared.global [%0], [%1], 16;\n" :: "r"(saddr), "l"(g));
}
__device__ __forceinline__ void cp_commit() { asm volatile("cp.async.commit_group;\n"); }
template <int N> __device__ __forceinline__ void cp_wait() {
    asm volatile("cp.async.wait_group %0;\n" :: "n"(N));
}
#define SWZ(o) ((o) ^ (((o) >> 3) & 0x70))

__device__ __forceinline__ uint32_t elect_one_pred() {
    uint32_t pred;
    asm volatile(
        "{\n\t.reg .pred p;\n\t"
        "elect.sync _|p, 0xFFFFFFFF;\n\t"
        "selp.b32 %0, 1, 0, p;\n\t}"
        : "=r"(pred));
    return pred;
}

// =====================================================================
// Kernel 1: router  (UNCHANGED — its fp32 reduction order defines the
// argmax permutation that matches the reference; do not perturb)
// =====================================================================
__global__ __launch_bounds__(256) void router_kernel(
    const float* __restrict__ x, const float* __restrict__ Wr,
    const float* __restrict__ br, int T)
{
    __shared__ float sW[E_DIM][H_DIM];
    for (int i = threadIdx.x; i < H_DIM * E_DIM; i += 256) {
        int h = i >> 3, e = i & 7;
        sW[e][h] = Wr[i];
    }
    __syncthreads();

    int warp = threadIdx.x >> 5;
    int lane = threadIdx.x & 31;
    int tokBase = blockIdx.x * 32 + warp * 4;

    for (int tt = 0; tt < 4; ++tt) {
        int t = tokBase + tt;
        if (t >= T) break;
        const float* xr = x + (size_t)t * H_DIM;

        float acc[E_DIM];
        #pragma unroll
        for (int e = 0; e < E_DIM; ++e) acc[e] = 0.f;
        #pragma unroll 4
        for (int i = 0; i < H_DIM / 32; ++i) {
            float xv = xr[i * 32 + lane];
            #pragma unroll
            for (int e = 0; e < E_DIM; ++e) acc[e] += xv * sW[e][i * 32 + lane];
        }
        #pragma unroll
        for (int e = 0; e < E_DIM; ++e) {
            #pragma unroll
            for (int off = 16; off; off >>= 1)
                acc[e] += __shfl_down_sync(0xffffffffu, acc[e], off);
        }
        if (lane == 0) {
            float l[E_DIM];
            #pragma unroll
            for (int e = 0; e < E_DIM; ++e) l[e] = acc[e] + br[e];
            int bi = 0; float bm = l[0];
            #pragma unroll
            for (int e = 1; e < E_DIM; ++e)
                if (l[e] > bm) { bm = l[e]; bi = e; }
            float s = 0.f;
            #pragma unroll
            for (int e = 0; e < E_DIM; ++e) s += expf(l[e] - bm);
            g_best [t] = bi;
            g_bestp[t] = 1.0f / s;
        }
    }
}

// =====================================================================
// Kernel 2: per-block histograms
// =====================================================================
__global__ void hist_kernel(int T)
{
    __shared__ int sh[E_DIM];
    if (threadIdx.x < E_DIM) sh[threadIdx.x] = 0;
    __syncthreads();
    int t = blockIdx.x * 256 + threadIdx.x;
    if (t < T) atomicAdd(&sh[g_best[t]], 1);
    __syncthreads();
    if (threadIdx.x < E_DIM)
        g_hist[blockIdx.x * E_DIM + threadIdx.x] = sh[threadIdx.x];
}

// =====================================================================
// Kernel 3: exclusive offsets — PARALLEL warp-scan (was 21us serial)
// One block, warp e scans column e across NB block-histograms.
// =====================================================================
__global__ __launch_bounds__(256) void offsets_kernel(int NB)
{
    __shared__ int sh[NB_MAX * E_DIM];   // 4 KB
    __shared__ int tot[E_DIM];
    __shared__ int base[E_DIM];
    const int tid = threadIdx.x;
    for (int i = tid; i < NB * E_DIM; i += 256) sh[i] = g_hist[i];
    __syncthreads();

    const int w = tid >> 5, l = tid & 31;
    if (w < E_DIM) {
        int run = 0;
        for (int c = 0; c < NB; c += 32) {
            int v = sh[(c + l) * E_DIM + w];
            int xs = v;
            #pragma unroll
            for (int off = 1; off < 32; off <<= 1) {
                int y = __shfl_up_sync(0xffffffffu, xs, off);
                if (l >= off) xs += y;
            }
            sh[(c + l) * E_DIM + w] = xs - v + run;   // exclusive
            run += __shfl_sync(0xffffffffu, xs, 31);
        }
        if (l == 0) tot[w] = run;
    }
    __syncthreads();
    if (tid == 0) {
        int b = 0;
        #pragma unroll
        for (int e = 0; e < E_DIM; ++e) { base[e] = b; b += tot[e]; }
    }
    __syncthreads();
    for (int i = tid; i < NB * E_DIM; i += 256)
        g_boff[i] = sh[i] + base[i & (E_DIM - 1)];
}

// =====================================================================
// Kernel 4: stable scatter
// =====================================================================
__global__ void scatter_kernel(int T)
{
    __shared__ int sb[256];
    int i = threadIdx.x;
    int t = blockIdx.x * 256 + i;
    sb[i] = (t < T) ? g_best[t] : -1;
    __syncthreads();
    if (t < T) {
        int e = sb[i];
        int rank = 0;
        for (int j = 0; j < i; ++j) rank += (sb[j] == e);
        int pos = g_boff[blockIdx.x * E_DIM + e] + rank;
        g_order[pos] = t;
    }
}

// =====================================================================
// Kernel 5: gather permuted rows of x, RN-round to tf32
// =====================================================================
__global__ __launch_bounds__(256) void gather_round_kernel(const float* __restrict__ x)
{
    int t = blockIdx.x;
    int src = g_order[t];
    const float4* s = (const float4*)(x + (size_t)src * H_DIM);
    float4* d = (float4*)(g_A + (size_t)t * H_DIM);
    float4 v = s[threadIdx.x];
    v.x = round_tf32(v.x); v.y = round_tf32(v.y);
    v.z = round_tf32(v.z); v.w = round_tf32(v.w);
    d[threadIdx.x] = v;
}

// =====================================================================
// Kernel 6: transpose W_expert -> [N,K] with RN tf32 rounding
// =====================================================================
__global__ void transpose_round_kernel(const float* __restrict__ We)
{
    __shared__ float tile[32][33];
    int n = blockIdx.x * 32 + threadIdx.x;
    int k = blockIdx.y * 32 + threadIdx.y;
    tile[threadIdx.y][threadIdx.x] = round_tf32(We[(size_t)k * H_DIM + n]);
    __syncthreads();
    int on = blockIdx.x * 32 + threadIdx.y;
    int ok = blockIdx.y * 32 + threadIdx.x;
    g_Wt[(size_t)on * H_DIM + ok] = tile[threadIdx.x][threadIdx.y];
}

// =====================================================================
// tcgen05-only machinery
// =====================================================================
#if HAS_TCGEN05

#define MBARRIER_INIT(addr, cnt) \
    asm volatile("mbarrier.init.shared.b64 [%0], %1;" :: "r"((uint32_t)(addr)), "r"((uint32_t)(cnt)) : "memory")
#define MBARRIER_INVAL(addr) \
    asm volatile("mbarrier.inval.shared.b64 [%0];" :: "r"((uint32_t)(addr)) : "memory")
#define MBARRIER_WAIT_PARITY(mbar, parity) do {                                   \
    asm volatile(                                                                 \
        "{\n\t.reg .pred P1;\n\t"                                                 \
        "WAIT_LOOP_%=:\n\t"                                                       \
        "mbarrier.try_wait.parity.acquire.cta.shared::cta.b64 P1, [%0], %1, 0x989680;\n\t" \
        "@P1 bra.uni WAIT_DONE_%=;\n\t"                                           \
        "bra.uni WAIT_LOOP_%=;\n\t"                                               \
        "WAIT_DONE_%=:\n\t}"                                                      \
        :: "r"((uint32_t)(mbar)), "r"((uint32_t)(parity)) : "memory");            \
} while (0)

#define TCGEN05_ALLOC(sres, n) \
    asm volatile("tcgen05.alloc.cta_group::1.sync.aligned.shared::cta.b32 [%0], %1;" \
                 :: "r"((uint32_t)(sres)), "r"((uint32_t)(n)) : "memory")
#define TCGEN05_DEALLOC(tm, n) \
    asm volatile("tcgen05.dealloc.cta_group::1.sync.aligned.b32 %0, %1;" :: "r"(tm), "r"((uint32_t)(n)))
#define TCGEN05_COMMIT(mbar) \
    asm volatile("tcgen05.commit.cta_group::1.mbarrier::arrive::one.shared::cluster.b64 [%0];" \
                 :: "r"((uint32_t)(mbar)) : "memory")
#define TCGEN05_FENCE_AFTER()  asm volatile("tcgen05.fence::after_thread_sync;" ::: "memory")
#define TCGEN05_FENCE_BEFORE() asm volatile("tcgen05.fence::before_thread_sync;" ::: "memory")
#define TCGEN05_WAIT_LD()      asm volatile("tcgen05.wait::ld.sync.aligned;" ::: "memory")
#define FENCE_PROXY_ASYNC()    asm volatile("fence.proxy.async.shared::cta;" ::: "memory")

#define TCGEN05_LD_32X32B_X32(r, tmem_addr)                                     \
    asm volatile(                                                               \
        "tcgen05.ld.sync.aligned.32x32b.x32.b32 "                               \
        "{%0, %1, %2, %3, %4, %5, %6, %7, "                                     \
        " %8, %9, %10, %11, %12, %13, %14, %15, "                               \
        " %16, %17, %18, %19, %20, %21, %22, %23, "                             \
        " %24, %25, %26, %27, %28, %29, %30, %31}, [%32];"                      \
        : "=r"((r)[0]),  "=r"((r)[1]),  "=r"((r)[2]),  "=r"((r)[3]),            \
          "=r"((r)[4]),  "=r"((r)[5]),  "=r"((r)[6]),  "=r"((r)[7]),            \
          "=r"((r)[8]),  "=r"((r)[9]),  "=r"((r)[10]), "=r"((r)[11]),           \
          "=r"((r)[12]), "=r"((r)[13]), "=r"((r)[14]), "=r"((r)[15]),           \
          "=r"((r)[16]), "=r"((r)[17]), "=r"((r)[18]), "=r"((r)[19]),           \
          "=r"((r)[20]), "=r"((r)[21]), "=r"((r)[22]), "=r"((r)[23]),           \
          "=r"((r)[24]), "=r"((r)[25]), "=r"((r)[26]), "=r"((r)[27]),           \
          "=r"((r)[28]), "=r"((r)[29]), "=r"((r)[30]), "=r"((r)[31])            \
        : "r"(tmem_addr))

static constexpr uint64_t SMEM_DESC_BASE_SW128 =
    (uint64_t(2)  << 61) | (uint64_t(1) << 46) | (uint64_t(64) << 32) | (uint64_t(1) << 16);
#define MAKE_SMEM_DESC(base) (SMEM_DESC_BASE_SW128 | ((uint64_t)((base) >> 4) & 0x3FFF))

// idesc kind::tf32 SS cg1: d=F32(1<<4), a=TF32(2<<7), b=TF32(2<<10),
// (N=256/8)<<17, (M=128/16)<<24.
#define GEMM_IDESC 0x8400910u

__device__ __forceinline__ void mma_tf32_ss(uint32_t d, uint64_t a, uint64_t b, uint32_t en) {
    asm volatile(
        "{\n\t.reg .pred p;\n\t"
        "setp.ne.u32 p, %4, 0;\n\t"
        "tcgen05.mma.cta_group::1.kind::tf32 [%0], %1, %2, %3, {%5, %5, %5, %5}, p;\n\t}"
        :: "r"(d), "l"(a), "l"(b), "r"(GEMM_IDESC), "r"(en), "r"(0u) : "memory");
}
#endif  // HAS_TCGEN05

// =====================================================================
// Kernel 7a: tcgen05 tf32 GEMM, 256x256 tile via 2x (M=128,N=256) MMAs
// sharing one B tile; D0 at TMEM col 0, D1 at col 256. 3-stage pipeline.
// =====================================================================
#define GBM 256
#define GBN 256
#define GBK 32
#define A_STAGE (GBM * GBK * 4)            // 32768 B
#define B_STAGE (GBN * GBK * 4)            // 32768 B
#define STAGE_BYTES (A_STAGE + B_STAGE)    // 65536 B
#define NSTAGES 3
#define GEMM_SMEM (4096 + NSTAGES * STAGE_BYTES)   // ~200 KB

__global__ __launch_bounds__(256)
#if HAS_TCGEN05
__cluster_dims__(1, 1, 1)
#endif
void gemm_tc_kernel(const float* __restrict__ be, float* __restrict__ out)
{
#if HAS_TCGEN05
    extern __shared__ char smem[];
    uint32_t sb = smem_u32(smem);
    const int tid  = threadIdx.x;
    const int wid  = tid >> 5;
    const int lane = tid & 31;
    const int rowBase = blockIdx.y * GBM;
    const int colBase = blockIdx.x * GBN;

    float* sBias = (float*)(smem + 64);     // 256 f32 -> [64, 1088)
    float* sBp   = (float*)(smem + 1088);   // 256 f32 -> [1088, 2112)
    const uint32_t buf0 = (sb + 2112 + 1023) & ~1023u;

    if (wid == 0) {
        TCGEN05_ALLOC(sb + 0, 512);
        if (elect_one_pred()) {
            MBARRIER_INIT(sb + 8, 1);
            MBARRIER_INIT(sb + 16, 1);
            MBARRIER_INIT(sb + 24, 1);
        }
    }
    sBias[tid] = be[colBase + tid];
    sBp[tid]   = g_bestp[rowBase + tid];
    __syncthreads();
    uint32_t tmem;
    asm volatile("ld.shared.b32 %0, [%1];" : "=r"(tmem) : "r"(sb + 0));

    const float* Abase = g_A  + (size_t)rowBase * H_DIM;
    const float* Bbase = g_Wt + (size_t)colBase * H_DIM;

    // per stage: A = 256 rows x 128B (2048 cp16), B = 256 rows x 128B (2048 cp16)
    auto load_stage = [&](int buf, int kt) {
        const int k0 = kt * GBK;
        const uint32_t ab = buf0 + buf * STAGE_BYTES;
        const uint32_t bb = ab + A_STAGE;
        #pragma unroll
        for (int j = 0; j < 8; ++j) {
            int idx = tid + j * 256;
            int r = idx >> 3, s = idx & 7;
            cp16(ab + SWZ(r * 128 + s * 16), Abase + (size_t)r * H_DIM + k0 + s * 4);
        }
        #pragma unroll
        for (int j = 0; j < 8; ++j) {
            int idx = tid + j * 256;
            int r = idx >> 3, s = idx & 7;
            cp16(bb + SWZ(r * 128 + s * 16), Bbase + (size_t)r * H_DIM + k0 + s * 4);
        }
    };

    int ph[NSTAGES] = {0, 0, 0};
    load_stage(0, 0); cp_commit();
    load_stage(1, 1); cp_commit();

    const int NST = H_DIM / GBK;   // 32
    for (int kt = 0; kt < NST; ++kt) {
        const int cur = kt % NSTAGES;
        if (kt + 2 < NST) {
            const int nb = (kt + 2) % NSTAGES;
            if (kt >= 1) {  // MMA of stage kt-1 used buffer nb; wait before overwrite
                MBARRIER_WAIT_PARITY(sb + 8 + nb * 8, ph[nb]);
                ph[nb] ^= 1;
            }
            load_stage(nb, kt + 2);
            cp_commit();
            cp_wait<2>();        // stage kt resident (2 newer groups may be in flight)
        } else if (kt + 1 < NST) {
            cp_wait<1>();        // only stage kt+1 in flight
        } else {
            cp_wait<0>();
        }
        FENCE_PROXY_ASYNC();
        __syncthreads();

        if (wid == 0) {
            if (elect_one_pred()) {
                const uint32_t ab = buf0 + cur * STAGE_BYTES;
                uint64_t ad0 = MAKE_SMEM_DESC(ab);
                uint64_t ad1 = MAKE_SMEM_DESC(ab + 128 * 128);  // rows 128..255
                uint64_t bd  = MAKE_SMEM_DESC(ab + A_STAGE);
                #pragma unroll
                for (int ks = 0; ks < 4; ++ks) {
                    uint32_t en = (kt | ks) != 0;
                    mma_tf32_ss(tmem,       ad0 + ks * 2, bd + ks * 2, en);
                    mma_tf32_ss(tmem + 256, ad1 + ks * 2, bd + ks * 2, en);
                }
                TCGEN05_COMMIT(sb + 8 + cur * 8);
            }
        }
    }

    // drain: each buffer has exactly one unconsumed commit at current parity
    MBARRIER_WAIT_PARITY(sb + 8,  ph[0]);
    MBARRIER_WAIT_PARITY(sb + 16, ph[1]);
    MBARRIER_WAIT_PARITY(sb + 24, ph[2]);
    TCGEN05_FENCE_AFTER();

    // epilogue: warps 0-3 -> D0 (tile rows 0-127), warps 4-7 -> D1 (rows 128-255)
    {
        const int half   = wid >> 2;                 // 0 or 1
        const int rowLoc = half * 128 + (wid & 3) * 32 + lane;
        const float p = sBp[rowLoc];
        const uint32_t dbase = tmem + half * 256;
        float* orow = out + (size_t)(rowBase + rowLoc) * H_DIM + colBase;
        #pragma unroll
        for (int ch = 0; ch < 8; ++ch) {
            uint32_t r[32];
            TCGEN05_LD_32X32B_X32(r, dbase + ch * 32);
            TCGEN05_WAIT_LD();
            #pragma unroll
            for (int i = 0; i < 32; i += 4) {
                float4 v;
                v.x = (__uint_as_float(r[i + 0]) + sBias[ch * 32 + i + 0]) * p;
                v.y = (__uint_as_float(r[i + 1]) + sBias[ch * 32 + i + 1]) * p;
                v.z = (__uint_as_float(r[i + 2]) + sBias[ch * 32 + i + 2]) * p;
                v.w = (__uint_as_float(r[i + 3]) + sBias[ch * 32 + i + 3]) * p;
                *(float4*)(orow + ch * 32 + i) = v;
            }
        }
        TCGEN05_FENCE_BEFORE();
    }
    __syncthreads();
    if (wid == 0) {
        if (elect_one_pred()) {
            MBARRIER_INVAL(sb + 8); MBARRIER_INVAL(sb + 16); MBARRIER_INVAL(sb + 24);
        }
        TCGEN05_DEALLOC(tmem, 512);
    }
#endif  // HAS_TCGEN05
}

// =====================================================================
// Kernel 7b: WMMA tf32 fallback 128x128 (compiled in ALL passes)
// =====================================================================
#define FBM 128
#define FBN 128
#define FBK 16
#define FLD 20
#define FNKT (H_DIM / FBK)
#define FB_SMEM (( (2*FBM*FLD) + (2*FBN*FLD) + 8*256 + FBM + FBN ) * 4)

__global__ __launch_bounds__(256) void gemm_wmma_kernel(
    const float* __restrict__ be, float* __restrict__ out)
{
    extern __shared__ float fsm[];
    float* As    = fsm;
    float* Bs    = As + 2 * FBM * FLD;
    float* sC    = Bs + 2 * FBN * FLD;
    float* sBias = sC + 8 * 256;
    float* sBp   = sBias + FBN;

    const int tid = threadIdx.x;
    const int rowBase = blockIdx.y * FBM;
    const int colBase = blockIdx.x * FBN;

    if (tid < FBM)       sBp[tid]         = g_bestp[rowBase + tid];
    else                 sBias[tid - FBM] = be[colBase + tid - FBM];

    const int arow = tid >> 1;
    const int aseg = (tid & 1) * 8;
    const float* aSrc = g_A  + (size_t)(rowBase + arow) * H_DIM + aseg;
    const float* bSrc = g_Wt + (size_t)(colBase + arow) * H_DIM + aseg;
    const uint32_t asm_base = smem_u32(As);
    const uint32_t bsm_base = smem_u32(Bs);

    auto load_tiles = [&](int buf, int kt) {
        const int k0 = kt * FBK;
        uint32_t ao = asm_base + (buf * FBM * FLD + arow * FLD + aseg) * 4;
        uint32_t bo = bsm_base + (buf * FBN * FLD + arow * FLD + aseg) * 4;
        cp16(ao,      aSrc + k0);
        cp16(ao + 16, aSrc + k0 + 4);
        cp16(bo,      bSrc + k0);
        cp16(bo + 16, bSrc + k0 + 4);
    };

    const int warpId = tid >> 5;
    const int wm = warpId >> 2;
    const int wn = warpId & 3;

    wmma::fragment<wmma::accumulator, 16, 16, 8, float> acc[4][2];
    #pragma unroll
    for (int mi = 0; mi < 4; ++mi)
        #pragma unroll
        for (int ni = 0; ni < 2; ++ni)
            wmma::fill_fragment(acc[mi][ni], 0.0f);

    load_tiles(0, 0);
    cp_commit();

    for (int kt = 0; kt < FNKT; ++kt) {
        if (kt + 1 < FNKT) {
            load_tiles((kt + 1) & 1, kt + 1);
            cp_commit();
            cp_wait<1>();
        } else {
            cp_wait<0>();
        }
        __syncthreads();

        const int buf = kt & 1;
        #pragma unroll
        for (int ks = 0; ks < 2; ++ks) {
            wmma::fragment<wmma::matrix_a, 16, 16, 8, wmma::precision::tf32,
                           wmma::row_major> af[4];
            wmma::fragment<wmma::matrix_b, 16, 16, 8, wmma::precision::tf32,
                           wmma::col_major> bf[2];
            #pragma unroll
            for (int mi = 0; mi < 4; ++mi)
                wmma::load_matrix_sync(
                    af[mi], &As[buf * FBM * FLD + (wm * 64 + mi * 16) * FLD + ks * 8], FLD);
            #pragma unroll
            for (int ni = 0; ni < 2; ++ni)
                wmma::load_matrix_sync(
                    bf[ni], &Bs[buf * FBN * FLD + (wn * 32 + ni * 16) * FLD + ks * 8], FLD);
            #pragma unroll
            for (int mi = 0; mi < 4; ++mi)
                #pragma unroll
                for (int ni = 0; ni < 2; ++ni)
                    wmma::mma_sync(acc[mi][ni], af[mi], bf[ni], acc[mi][ni]);
        }
        __syncthreads();
    }

    const int lane = tid & 31;
    float* stg = &sC[warpId * 256];
    #pragma unroll
    for (int mi = 0; mi < 4; ++mi) {
        #pragma unroll
        for (int ni = 0; ni < 2; ++ni) {
            wmma::store_matrix_sync(stg, acc[mi][ni], 16, wmma::mem_row_major);
            __syncwarp();
            const int r = lane >> 1;
            const int c = (lane & 1) * 8;
            const int rowL = wm * 64 + mi * 16 + r;
            const int colL = wn * 32 + ni * 16 + c;
            const float p = sBp[rowL];
            float4 v0 = *(const float4*)&stg[r * 16 + c];
            float4 v1 = *(const float4*)&stg[r * 16 + c + 4];
            float4 o0, o1;
            o0.x = (v0.x + sBias[colL + 0]) * p;
            o0.y = (v0.y + sBias[colL + 1]) * p;
            o0.z = (v0.z + sBias[colL + 2]) * p;
            o0.w = (v0.w + sBias[colL + 3]) * p;
            o1.x = (v1.x + sBias[colL + 4]) * p;
            o1.y = (v1.y + sBias[colL + 5]) * p;
            o1.z = (v1.z + sBias[colL + 6]) * p;
            o1.w = (v1.w + sBias[colL + 7]) * p;
            float* dst = out + (size_t)(rowBase + rowL) * H_DIM + colBase + colL;
            *(float4*)(dst + 0) = o0;
            *(float4*)(dst + 4) = o1;
            __syncwarp();
        }
    }
}

// =====================================================================
// launch
// =====================================================================
extern "C" void kernel_launch(void* const* d_in, const int* in_sizes, int n_in,
                              void* d_out, int out_size)
{
    const float* x  = (const float*)d_in[0];
    const float* Wr = (const float*)d_in[1];
    const float* br = (const float*)d_in[2];
    const float* We = (const float*)d_in[3];
    const float* be = (const float*)d_in[4];
    float* out = (float*)d_out;

    const int T  = in_sizes[0] / H_DIM;   // 32768
    const int NB = T / 256;

    router_kernel<<<T / 32, 256>>>(x, Wr, br, T);
    transpose_round_kernel<<<dim3(H_DIM / 32, H_DIM / 32), dim3(32, 32)>>>(We);
    hist_kernel<<<NB, 256>>>(T);
    offsets_kernel<<<1, 256>>>(NB);
    scatter_kernel<<<NB, 256>>>(T);
    gather_round_kernel<<<T, 256>>>(x);

    cudaFuncAttributes attr;
    attr.numRegs = 0;
    cudaFuncGetAttributes(&attr, (const void*)gemm_tc_kernel);

    if (attr.numRegs > 32) {
        cudaFuncSetAttribute(gemm_tc_kernel,
                             cudaFuncAttributeMaxDynamicSharedMemorySize, GEMM_SMEM);
        dim3 gtc(H_DIM / GBN, T / GBM);   // (4, 128)
        gemm_tc_kernel<<<gtc, 256, GEMM_SMEM>>>(be, out);
    } else {
        cudaFuncSetAttribute(gemm_wmma_kernel,
                             cudaFuncAttributeMaxDynamicSharedMemorySize, FB_SMEM);
        dim3 gfb(H_DIM / FBN, T / FBM);   // (8, 256)
        gemm_wmma_kernel<<<gfb, 256, FB_SMEM>>>(be, out);
    }
}

// round 6
// speedup vs baseline: 3.8012x; 1.1722x over previous
#include <cuda_runtime.h>
#include <cuda.h>
#include <mma.h>
#include <cstdint>

using namespace nvcuda;

#define T_MAX 32768
#define H_DIM 1024
#define E_DIM 8

// tcgen05 is only legal in arch-accelerated (sm_10xa) compilation passes.
#if defined(__CUDA_ARCH_FEAT_SM103_ALL) || defined(__CUDA_ARCH_FEAT_SM100_ALL) || defined(__CUDA_ARCH_FEAT_SM101_ALL)
#define HAS_TCGEN05 1
#else
#define HAS_TCGEN05 0
#endif

// ---------------- scratch (no runtime allocations allowed) ----------------
__device__ int   g_best [T_MAX];
__device__ float g_bestp[T_MAX];
__device__ int   g_order[T_MAX];
#define NB_MAX (T_MAX / 256)
__device__ int g_hist[NB_MAX * E_DIM];
__device__ int g_boff[NB_MAX * E_DIM];
__device__ float g_A [T_MAX * H_DIM];   // gathered + RN-rounded-to-tf32 activations
__device__ float g_Wt[H_DIM * H_DIM];   // W_expert transposed ([N,K]) + RN tf32

// ---------------- generic helpers ----------------
__device__ __forceinline__ uint32_t smem_u32(const void* p) {
    uint32_t a;
    asm("{ .reg .u64 t; cvta.to.shared.u64 t, %1; cvt.u32.u64 %0, t; }" : "=r"(a) : "l"(p));
    return a;
}
__device__ __forceinline__ float round_tf32(float v) {
    uint32_t o;
    asm("cvt.rna.tf32.f32 %0, %1;" : "=r"(o) : "f"(v));
    return __uint_as_float(o);
}
__device__ __forceinline__ void cp16(uint32_t saddr, const void* g) {
    asm volatile("cp.async.cg.shared.global [%0], [%1], 16;\n" :: "r"(saddr), "l"(g));
}
__device__ __forceinline__ void cp_commit() { asm volatile("cp.async.commit_group;\n"); }
template <int N> __device__ __forceinline__ void cp_wait() {
    asm volatile("cp.async.wait_group %0;\n" :: "n"(N));
}

__device__ __forceinline__ uint32_t elect_one_pred() {
    uint32_t pred;
    asm volatile(
        "{\n\t.reg .pred p;\n\t"
        "elect.sync _|p, 0xFFFFFFFF;\n\t"
        "selp.b32 %0, 1, 0, p;\n\t}"
        : "=r"(pred));
    return pred;
}

// =====================================================================
// Kernel 1: router (UNCHANGED — fp32 order defines the permutation)
// =====================================================================
__global__ __launch_bounds__(256) void router_kernel(
    const float* __restrict__ x, const float* __restrict__ Wr,
    const float* __restrict__ br, int T)
{
    __shared__ float sW[E_DIM][H_DIM];
    for (int i = threadIdx.x; i < H_DIM * E_DIM; i += 256) {
        int h = i >> 3, e = i & 7;
        sW[e][h] = Wr[i];
    }
    __syncthreads();

    int warp = threadIdx.x >> 5;
    int lane = threadIdx.x & 31;
    int tokBase = blockIdx.x * 32 + warp * 4;

    for (int tt = 0; tt < 4; ++tt) {
        int t = tokBase + tt;
        if (t >= T) break;
        const float* xr = x + (size_t)t * H_DIM;

        float acc[E_DIM];
        #pragma unroll
        for (int e = 0; e < E_DIM; ++e) acc[e] = 0.f;
        #pragma unroll 4
        for (int i = 0; i < H_DIM / 32; ++i) {
            float xv = xr[i * 32 + lane];
            #pragma unroll
            for (int e = 0; e < E_DIM; ++e) acc[e] += xv * sW[e][i * 32 + lane];
        }
        #pragma unroll
        for (int e = 0; e < E_DIM; ++e) {
            #pragma unroll
            for (int off = 16; off; off >>= 1)
                acc[e] += __shfl_down_sync(0xffffffffu, acc[e], off);
        }
        if (lane == 0) {
            float l[E_DIM];
            #pragma unroll
            for (int e = 0; e < E_DIM; ++e) l[e] = acc[e] + br[e];
            int bi = 0; float bm = l[0];
            #pragma unroll
            for (int e = 1; e < E_DIM; ++e)
                if (l[e] > bm) { bm = l[e]; bi = e; }
            float s = 0.f;
            #pragma unroll
            for (int e = 0; e < E_DIM; ++e) s += expf(l[e] - bm);
            g_best [t] = bi;
            g_bestp[t] = 1.0f / s;
        }
    }
}

// =====================================================================
// Kernels 2-4: stable counting sort
// =====================================================================
__global__ void hist_kernel(int T)
{
    __shared__ int sh[E_DIM];
    if (threadIdx.x < E_DIM) sh[threadIdx.x] = 0;
    __syncthreads();
    int t = blockIdx.x * 256 + threadIdx.x;
    if (t < T) atomicAdd(&sh[g_best[t]], 1);
    __syncthreads();
    if (threadIdx.x < E_DIM)
        g_hist[blockIdx.x * E_DIM + threadIdx.x] = sh[threadIdx.x];
}

__global__ __launch_bounds__(256) void offsets_kernel(int NB)
{
    __shared__ int sh[NB_MAX * E_DIM];
    __shared__ int tot[E_DIM];
    __shared__ int base[E_DIM];
    const int tid = threadIdx.x;
    for (int i = tid; i < NB * E_DIM; i += 256) sh[i] = g_hist[i];
    __syncthreads();

    const int w = tid >> 5, l = tid & 31;
    if (w < E_DIM) {
        int run = 0;
        for (int c = 0; c < NB; c += 32) {
            int v = sh[(c + l) * E_DIM + w];
            int xs = v;
            #pragma unroll
            for (int off = 1; off < 32; off <<= 1) {
                int y = __shfl_up_sync(0xffffffffu, xs, off);
                if (l >= off) xs += y;
            }
            sh[(c + l) * E_DIM + w] = xs - v + run;
            run += __shfl_sync(0xffffffffu, xs, 31);
        }
        if (l == 0) tot[w] = run;
    }
    __syncthreads();
    if (tid == 0) {
        int b = 0;
        #pragma unroll
        for (int e = 0; e < E_DIM; ++e) { base[e] = b; b += tot[e]; }
    }
    __syncthreads();
    for (int i = tid; i < NB * E_DIM; i += 256)
        g_boff[i] = sh[i] + base[i & (E_DIM - 1)];
}

__global__ void scatter_kernel(int T)
{
    __shared__ int sb[256];
    int i = threadIdx.x;
    int t = blockIdx.x * 256 + i;
    sb[i] = (t < T) ? g_best[t] : -1;
    __syncthreads();
    if (t < T) {
        int e = sb[i];
        int rank = 0;
        for (int j = 0; j < i; ++j) rank += (sb[j] == e);
        int pos = g_boff[blockIdx.x * E_DIM + e] + rank;
        g_order[pos] = t;
    }
}

// =====================================================================
// Kernel 5: gather + RN-round to tf32
// =====================================================================
__global__ __launch_bounds__(256) void gather_round_kernel(const float* __restrict__ x)
{
    int t = blockIdx.x;
    int src = g_order[t];
    const float4* s = (const float4*)(x + (size_t)src * H_DIM);
    float4* d = (float4*)(g_A + (size_t)t * H_DIM);
    float4 v = s[threadIdx.x];
    v.x = round_tf32(v.x); v.y = round_tf32(v.y);
    v.z = round_tf32(v.z); v.w = round_tf32(v.w);
    d[threadIdx.x] = v;
}

// =====================================================================
// Kernel 6: transpose W_expert -> [N,K] with RN tf32 rounding
// =====================================================================
__global__ void transpose_round_kernel(const float* __restrict__ We)
{
    __shared__ float tile[32][33];
    int n = blockIdx.x * 32 + threadIdx.x;
    int k = blockIdx.y * 32 + threadIdx.y;
    tile[threadIdx.y][threadIdx.x] = round_tf32(We[(size_t)k * H_DIM + n]);
    __syncthreads();
    int on = blockIdx.x * 32 + threadIdx.y;
    int ok = blockIdx.y * 32 + threadIdx.x;
    g_Wt[(size_t)on * H_DIM + ok] = tile[threadIdx.x][threadIdx.y];
}

// =====================================================================
// tcgen05-only machinery
// =====================================================================
#if HAS_TCGEN05

#define MBARRIER_INIT(addr, cnt) \
    asm volatile("mbarrier.init.shared.b64 [%0], %1;" :: "r"((uint32_t)(addr)), "r"((uint32_t)(cnt)) : "memory")
#define MBARRIER_INVAL(addr) \
    asm volatile("mbarrier.inval.shared.b64 [%0];" :: "r"((uint32_t)(addr)) : "memory")
#define MBARRIER_EXPECT_TX(addr, bytes) \
    asm volatile("mbarrier.arrive.expect_tx.shared.b64 _, [%0], %1;" \
                 :: "r"((uint32_t)(addr)), "r"((uint32_t)(bytes)) : "memory")
#define MBARRIER_WAIT_PARITY(mbar, parity) do {                                   \
    asm volatile(                                                                 \
        "{\n\t.reg .pred P1;\n\t"                                                 \
        "WAIT_LOOP_%=:\n\t"                                                       \
        "mbarrier.try_wait.parity.acquire.cta.shared::cta.b64 P1, [%0], %1, 0x989680;\n\t" \
        "@P1 bra.uni WAIT_DONE_%=;\n\t"                                           \
        "bra.uni WAIT_LOOP_%=;\n\t"                                               \
        "WAIT_DONE_%=:\n\t}"                                                      \
        :: "r"((uint32_t)(mbar)), "r"((uint32_t)(parity)) : "memory");            \
} while (0)

#define TCGEN05_ALLOC(sres, n) \
    asm volatile("tcgen05.alloc.cta_group::1.sync.aligned.shared::cta.b32 [%0], %1;" \
                 :: "r"((uint32_t)(sres)), "r"((uint32_t)(n)) : "memory")
#define TCGEN05_DEALLOC(tm, n) \
    asm volatile("tcgen05.dealloc.cta_group::1.sync.aligned.b32 %0, %1;" :: "r"(tm), "r"((uint32_t)(n)))
#define TCGEN05_COMMIT(mbar) \
    asm volatile("tcgen05.commit.cta_group::1.mbarrier::arrive::one.shared::cluster.b64 [%0];" \
                 :: "r"((uint32_t)(mbar)) : "memory")
#define TCGEN05_FENCE_AFTER()  asm volatile("tcgen05.fence::after_thread_sync;" ::: "memory")
#define TCGEN05_FENCE_BEFORE() asm volatile("tcgen05.fence::before_thread_sync;" ::: "memory")
#define TCGEN05_WAIT_LD()      asm volatile("tcgen05.wait::ld.sync.aligned;" ::: "memory")

#define TMA_LOAD_2D(smem_addr, tmap, cx, cy, mbar)                                \
    asm volatile(                                                                 \
        "cp.async.bulk.tensor.2d.shared::cta.global.tile.mbarrier::complete_tx::bytes " \
        "[%0], [%1, {%2, %3}], [%4];"                                             \
        :: "r"((uint32_t)(smem_addr)), "l"(tmap), "r"((int32_t)(cx)),             \
           "r"((int32_t)(cy)), "r"((uint32_t)(mbar)) : "memory")

#define TCGEN05_LD_32X32B_X32(r, tmem_addr)                                     \
    asm volatile(                                                               \
        "tcgen05.ld.sync.aligned.32x32b.x32.b32 "                               \
        "{%0, %1, %2, %3, %4, %5, %6, %7, "                                     \
        " %8, %9, %10, %11, %12, %13, %14, %15, "                               \
        " %16, %17, %18, %19, %20, %21, %22, %23, "                             \
        " %24, %25, %26, %27, %28, %29, %30, %31}, [%32];"                      \
        : "=r"((r)[0]),  "=r"((r)[1]),  "=r"((r)[2]),  "=r"((r)[3]),            \
          "=r"((r)[4]),  "=r"((r)[5]),  "=r"((r)[6]),  "=r"((r)[7]),            \
          "=r"((r)[8]),  "=r"((r)[9]),  "=r"((r)[10]), "=r"((r)[11]),           \
          "=r"((r)[12]), "=r"((r)[13]), "=r"((r)[14]), "=r"((r)[15]),           \
          "=r"((r)[16]), "=r"((r)[17]), "=r"((r)[18]), "=r"((r)[19]),           \
          "=r"((r)[20]), "=r"((r)[21]), "=r"((r)[22]), "=r"((r)[23]),           \
          "=r"((r)[24]), "=r"((r)[25]), "=r"((r)[26]), "=r"((r)[27]),           \
          "=r"((r)[28]), "=r"((r)[29]), "=r"((r)[30]), "=r"((r)[31])            \
        : "r"(tmem_addr))

static constexpr uint64_t SMEM_DESC_BASE_SW128 =
    (uint64_t(2)  << 61) | (uint64_t(1) << 46) | (uint64_t(64) << 32) | (uint64_t(1) << 16);
#define MAKE_SMEM_DESC(base) (SMEM_DESC_BASE_SW128 | ((uint64_t)((base) >> 4) & 0x3FFF))

// idesc kind::tf32 SS cg1: d=F32(1<<4), a=TF32(2<<7), b=TF32(2<<10),
// (N=256/8)<<17, (M=128/16)<<24.
#define GEMM_IDESC 0x8400910u

__device__ __forceinline__ void mma_tf32_ss(uint32_t d, uint64_t a, uint64_t b, uint32_t en) {
    asm volatile(
        "{\n\t.reg .pred p;\n\t"
        "setp.ne.u32 p, %4, 0;\n\t"
        "tcgen05.mma.cta_group::1.kind::tf32 [%0], %1, %2, %3, {%5, %5, %5, %5}, p;\n\t}"
        :: "r"(d), "l"(a), "l"(b), "r"(GEMM_IDESC), "r"(en), "r"(0u) : "memory");
}
#endif  // HAS_TCGEN05

// =====================================================================
// Kernel 7a: tcgen05 tf32 GEMM 256x256, TMA + warp-specialized pipeline
// warp0(elect)=MMA issuer, warp1(elect)=TMA producer; 3-stage ring.
// =====================================================================
#define GBM 256
#define GBN 256
#define GBK 32
#define A_STAGE (GBM * GBK * 4)            // 32768 B
#define B_STAGE (GBN * GBK * 4)            // 32768 B
#define STAGE_BYTES (A_STAGE + B_STAGE)    // 65536 B
#define NSTAGES 3
#define GEMM_SMEM (4096 + NSTAGES * STAGE_BYTES)

// mbar smem offsets (from sb):
//   0:   tmem ptr
//   8+16*s:  full[s]
//   64+16*s: empty[s]
//   120:  done
#define MB_FULL(s)  (sb + 8  + (s) * 16)
#define MB_EMPTY(s) (sb + 64 + (s) * 16)
#define MB_DONE     (sb + 120)

__global__ __launch_bounds__(256)
#if HAS_TCGEN05
__cluster_dims__(1, 1, 1)
#endif
void gemm_tc_kernel(const __grid_constant__ CUtensorMap tmA,
                    const __grid_constant__ CUtensorMap tmB,
                    const float* __restrict__ be, float* __restrict__ out)
{
#if HAS_TCGEN05
    extern __shared__ char smem[];
    uint32_t sb = smem_u32(smem);
    const int tid  = threadIdx.x;
    const int wid  = tid >> 5;
    const int lane = tid & 31;
    const int rowBase = blockIdx.y * GBM;
    const int colBase = blockIdx.x * GBN;

    float* sBias = (float*)(smem + 128);     // 256 f32 -> [128, 1152)
    float* sBp   = (float*)(smem + 1152);    // 256 f32 -> [1152, 2176)
    const uint32_t buf0 = (sb + 2176 + 1023) & ~1023u;

    if (wid == 0) TCGEN05_ALLOC(sb + 0, 512);
    if (tid == 0) {
        #pragma unroll
        for (int s = 0; s < NSTAGES; ++s) {
            MBARRIER_INIT(MB_FULL(s), 1);
            MBARRIER_INIT(MB_EMPTY(s), 1);
        }
        MBARRIER_INIT(MB_DONE, 1);
    }
    sBias[tid] = be[colBase + tid];
    sBp[tid]   = g_bestp[rowBase + tid];
    __syncthreads();
    uint32_t tmem;
    asm volatile("ld.shared.b32 %0, [%1];" : "=r"(tmem) : "r"(sb + 0));

    const int NST = H_DIM / GBK;   // 32

    if (wid == 1 && elect_one_pred()) {
        // ---------------- TMA producer ----------------
        int ph[NSTAGES] = {1, 1, 1};   // parity-1 start: first waits pass
        for (int kt = 0; kt < NST; ++kt) {
            const int s = kt % NSTAGES;
            MBARRIER_WAIT_PARITY(MB_EMPTY(s), ph[s]); ph[s] ^= 1;
            const uint32_t ab = buf0 + s * STAGE_BYTES;
            MBARRIER_EXPECT_TX(MB_FULL(s), STAGE_BYTES);
            TMA_LOAD_2D(ab,           &tmA, kt * GBK, rowBase, MB_FULL(s));
            TMA_LOAD_2D(ab + A_STAGE, &tmB, kt * GBK, colBase, MB_FULL(s));
        }
    }
    if (wid == 0 && elect_one_pred()) {
        // ---------------- MMA consumer ----------------
        int ph[NSTAGES] = {0, 0, 0};
        for (int kt = 0; kt < NST; ++kt) {
            const int s = kt % NSTAGES;
            MBARRIER_WAIT_PARITY(MB_FULL(s), ph[s]); ph[s] ^= 1;
            const uint32_t ab = buf0 + s * STAGE_BYTES;
            uint64_t ad0 = MAKE_SMEM_DESC(ab);
            uint64_t ad1 = MAKE_SMEM_DESC(ab + 128 * 128);   // rows 128..255
            uint64_t bd  = MAKE_SMEM_DESC(ab + A_STAGE);
            #pragma unroll
            for (int ks = 0; ks < 4; ++ks) {
                uint32_t en = (kt | ks) != 0;
                mma_tf32_ss(tmem,       ad0 + ks * 2, bd + ks * 2, en);
                mma_tf32_ss(tmem + 256, ad1 + ks * 2, bd + ks * 2, en);
            }
            TCGEN05_COMMIT(MB_EMPTY(s));
        }
        TCGEN05_COMMIT(MB_DONE);   // fires when ALL prior MMAs complete
    }

    // all threads: wait for every MMA to finish, then read D
    MBARRIER_WAIT_PARITY(MB_DONE, 0);
    TCGEN05_FENCE_AFTER();

    {
        const int half   = wid >> 2;                 // 0 or 1
        const int rowLoc = half * 128 + (wid & 3) * 32 + lane;
        const float p = sBp[rowLoc];
        const uint32_t dbase = tmem + half * 256;
        float* orow = out + (size_t)(rowBase + rowLoc) * H_DIM + colBase;
        #pragma unroll
        for (int ch = 0; ch < 8; ++ch) {
            uint32_t r[32];
            TCGEN05_LD_32X32B_X32(r, dbase + ch * 32);
            TCGEN05_WAIT_LD();
            #pragma unroll
            for (int i = 0; i < 32; i += 4) {
                float4 v;
                v.x = (__uint_as_float(r[i + 0]) + sBias[ch * 32 + i + 0]) * p;
                v.y = (__uint_as_float(r[i + 1]) + sBias[ch * 32 + i + 1]) * p;
                v.z = (__uint_as_float(r[i + 2]) + sBias[ch * 32 + i + 2]) * p;
                v.w = (__uint_as_float(r[i + 3]) + sBias[ch * 32 + i + 3]) * p;
                *(float4*)(orow + ch * 32 + i) = v;
            }
        }
        TCGEN05_FENCE_BEFORE();
    }
    __syncthreads();
    if (tid == 0) {
        #pragma unroll
        for (int s = 0; s < NSTAGES; ++s) {
            MBARRIER_INVAL(MB_FULL(s));
            MBARRIER_INVAL(MB_EMPTY(s));
        }
        MBARRIER_INVAL(MB_DONE);
    }
    __syncthreads();
    if (wid == 0) TCGEN05_DEALLOC(tmem, 512);
#endif  // HAS_TCGEN05
}

// =====================================================================
// Kernel 7b: WMMA tf32 fallback 128x128 (compiled in ALL passes)
// =====================================================================
#define FBM 128
#define FBN 128
#define FBK 16
#define FLD 20
#define FNKT (H_DIM / FBK)
#define FB_SMEM (( (2*FBM*FLD) + (2*FBN*FLD) + 8*256 + FBM + FBN ) * 4)

__global__ __launch_bounds__(256) void gemm_wmma_kernel(
    const float* __restrict__ be, float* __restrict__ out)
{
    extern __shared__ float fsm[];
    float* As    = fsm;
    float* Bs    = As + 2 * FBM * FLD;
    float* sC    = Bs + 2 * FBN * FLD;
    float* sBias = sC + 8 * 256;
    float* sBp   = sBias + FBN;

    const int tid = threadIdx.x;
    const int rowBase = blockIdx.y * FBM;
    const int colBase = blockIdx.x * FBN;

    if (tid < FBM)       sBp[tid]         = g_bestp[rowBase + tid];
    else                 sBias[tid - FBM] = be[colBase + tid - FBM];

    const int arow = tid >> 1;
    const int aseg = (tid & 1) * 8;
    const float* aSrc = g_A  + (size_t)(rowBase + arow) * H_DIM + aseg;
    const float* bSrc = g_Wt + (size_t)(colBase + arow) * H_DIM + aseg;
    const uint32_t asm_base = smem_u32(As);
    const uint32_t bsm_base = smem_u32(Bs);

    auto load_tiles = [&](int buf, int kt) {
        const int k0 = kt * FBK;
        uint32_t ao = asm_base + (buf * FBM * FLD + arow * FLD + aseg) * 4;
        uint32_t bo = bsm_base + (buf * FBN * FLD + arow * FLD + aseg) * 4;
        cp16(ao,      aSrc + k0);
        cp16(ao + 16, aSrc + k0 + 4);
        cp16(bo,      bSrc + k0);
        cp16(bo + 16, bSrc + k0 + 4);
    };

    const int warpId = tid >> 5;
    const int wm = warpId >> 2;
    const int wn = warpId & 3;

    wmma::fragment<wmma::accumulator, 16, 16, 8, float> acc[4][2];
    #pragma unroll
    for (int mi = 0; mi < 4; ++mi)
        #pragma unroll
        for (int ni = 0; ni < 2; ++ni)
            wmma::fill_fragment(acc[mi][ni], 0.0f);

    load_tiles(0, 0);
    cp_commit();

    for (int kt = 0; kt < FNKT; ++kt) {
        if (kt + 1 < FNKT) {
            load_tiles((kt + 1) & 1, kt + 1);
            cp_commit();
            cp_wait<1>();
        } else {
            cp_wait<0>();
        }
        __syncthreads();

        const int buf = kt & 1;
        #pragma unroll
        for (int ks = 0; ks < 2; ++ks) {
            wmma::fragment<wmma::matrix_a, 16, 16, 8, wmma::precision::tf32,
                           wmma::row_major> af[4];
            wmma::fragment<wmma::matrix_b, 16, 16, 8, wmma::precision::tf32,
                           wmma::col_major> bf[2];
            #pragma unroll
            for (int mi = 0; mi < 4; ++mi)
                wmma::load_matrix_sync(
                    af[mi], &As[buf * FBM * FLD + (wm * 64 + mi * 16) * FLD + ks * 8], FLD);
            #pragma unroll
            for (int ni = 0; ni < 2; ++ni)
                wmma::load_matrix_sync(
                    bf[ni], &Bs[buf * FBN * FLD + (wn * 32 + ni * 16) * FLD + ks * 8], FLD);
            #pragma unroll
            for (int mi = 0; mi < 4; ++mi)
                #pragma unroll
                for (int ni = 0; ni < 2; ++ni)
                    wmma::mma_sync(acc[mi][ni], af[mi], bf[ni], acc[mi][ni]);
        }
        __syncthreads();
    }

    const int lane = tid & 31;
    float* stg = &sC[warpId * 256];
    #pragma unroll
    for (int mi = 0; mi < 4; ++mi) {
        #pragma unroll
        for (int ni = 0; ni < 2; ++ni) {
            wmma::store_matrix_sync(stg, acc[mi][ni], 16, wmma::mem_row_major);
            __syncwarp();
            const int r = lane >> 1;
            const int c = (lane & 1) * 8;
            const int rowL = wm * 64 + mi * 16 + r;
            const int colL = wn * 32 + ni * 16 + c;
            const float p = sBp[rowL];
            float4 v0 = *(const float4*)&stg[r * 16 + c];
            float4 v1 = *(const float4*)&stg[r * 16 + c + 4];
            float4 o0, o1;
            o0.x = (v0.x + sBias[colL + 0]) * p;
            o0.y = (v0.y + sBias[colL + 1]) * p;
            o0.z = (v0.z + sBias[colL + 2]) * p;
            o0.w = (v0.w + sBias[colL + 3]) * p;
            o1.x = (v1.x + sBias[colL + 4]) * p;
            o1.y = (v1.y + sBias[colL + 5]) * p;
            o1.z = (v1.z + sBias[colL + 6]) * p;
            o1.w = (v1.w + sBias[colL + 7]) * p;
            float* dst = out + (size_t)(rowBase + rowL) * H_DIM + colBase + colL;
            *(float4*)(dst + 0) = o0;
            *(float4*)(dst + 4) = o1;
            __syncwarp();
        }
    }
}

// =====================================================================
// host: tensor-map construction via driver entry point (no -lcuda link)
// =====================================================================
typedef CUresult (*PFN_encodeTiled)(
    CUtensorMap*, CUtensorMapDataType, cuuint32_t, void*,
    const cuuint64_t*, const cuuint64_t*, const cuuint32_t*, const cuuint32_t*,
    CUtensorMapInterleave, CUtensorMapSwizzle, CUtensorMapL2promotion,
    CUtensorMapFloatOOBfill);

static PFN_encodeTiled get_encode_fn()
{
    void* fn = nullptr;
    cudaDriverEntryPointQueryResult qres = cudaDriverEntryPointSymbolNotFound;
#if CUDART_VERSION >= 12050
    cudaGetDriverEntryPointByVersion("cuTensorMapEncodeTiled", &fn, 12000,
                                     cudaEnableDefault, &qres);
#else
    cudaGetDriverEntryPoint("cuTensorMapEncodeTiled", &fn,
                            cudaEnableDefault, &qres);
#endif
    if (qres != cudaDriverEntryPointSuccess) return nullptr;
    return (PFN_encodeTiled)fn;
}

static bool make_map(PFN_encodeTiled enc, CUtensorMap* tm, void* base,
                     uint64_t d0, uint64_t d1, uint32_t b0, uint32_t b1)
{
    cuuint64_t dims[2]    = {d0, d1};
    cuuint64_t strides[1] = {d0 * 4};
    cuuint32_t box[2]     = {b0, b1};
    cuuint32_t es[2]      = {1, 1};
    CUresult r = enc(tm, CU_TENSOR_MAP_DATA_TYPE_FLOAT32, 2, base,
                     dims, strides, box, es,
                     CU_TENSOR_MAP_INTERLEAVE_NONE, CU_TENSOR_MAP_SWIZZLE_128B,
                     CU_TENSOR_MAP_L2_PROMOTION_L2_128B,
                     CU_TENSOR_MAP_FLOAT_OOB_FILL_NONE);
    return r == CUDA_SUCCESS;
}

// =====================================================================
// launch
// =====================================================================
extern "C" void kernel_launch(void* const* d_in, const int* in_sizes, int n_in,
                              void* d_out, int out_size)
{
    const float* x  = (const float*)d_in[0];
    const float* Wr = (const float*)d_in[1];
    const float* br = (const float*)d_in[2];
    const float* We = (const float*)d_in[3];
    const float* be = (const float*)d_in[4];
    float* out = (float*)d_out;

    const int T  = in_sizes[0] / H_DIM;   // 32768
    const int NB = T / 256;

    router_kernel<<<T / 32, 256>>>(x, Wr, br, T);
    transpose_round_kernel<<<dim3(H_DIM / 32, H_DIM / 32), dim3(32, 32)>>>(We);
    hist_kernel<<<NB, 256>>>(T);
    offsets_kernel<<<1, 256>>>(NB);
    scatter_kernel<<<NB, 256>>>(T);
    gather_round_kernel<<<T, 256>>>(x);

    // which GEMM variant is live in this binary?
    cudaFuncAttributes attr;
    attr.numRegs = 0;
    cudaFuncGetAttributes(&attr, (const void*)gemm_tc_kernel);

    bool tc_ok = (attr.numRegs > 32);
    CUtensorMap tmA, tmB;
    if (tc_ok) {
        PFN_encodeTiled enc = get_encode_fn();
        void *pA = nullptr, *pW = nullptr;
        tc_ok = enc != nullptr
             && cudaGetSymbolAddress(&pA, g_A)  == cudaSuccess
             && cudaGetSymbolAddress(&pW, g_Wt) == cudaSuccess
             && make_map(enc, &tmA, pA, H_DIM, (uint64_t)T, GBK, GBM)
             && make_map(enc, &tmB, pW, H_DIM, H_DIM,       GBK, GBN);
    }

    if (tc_ok) {
        cudaFuncSetAttribute(gemm_tc_kernel,
                             cudaFuncAttributeMaxDynamicSharedMemorySize, GEMM_SMEM);
        dim3 gtc(H_DIM / GBN, T / GBM);   // (4, 128)
        gemm_tc_kernel<<<gtc, 256, GEMM_SMEM>>>(tmA, tmB, be, out);
    } else {
        cudaFuncSetAttribute(gemm_wmma_kernel,
                             cudaFuncAttributeMaxDynamicSharedMemorySize, FB_SMEM);
        dim3 gfb(H_DIM / FBN, T / FBM);   // (8, 256)
        gemm_wmma_kernel<<<gfb, 256, FB_SMEM>>>(be, out);
    }
}